// round 17
// baseline (speedup 1.0000x reference)
#include <cuda_runtime.h>
#include <cstdint>

// Segment-mean over sorted segment ids.
// feats: [N, 128] f32, segment_ids: [N] i32 (sorted ascending), out: [S, 128] f32.
//
//   1) boundary_kernel: vectorized linear scan, one thread per 8 rows
//      (2x int4) fills g_seg_bounds; every entry written exactly once
//      (empty segments included). Signals PDL completion after its writes.
//   2) seg_mean_kernel: one warp per segment, TWO independent warps per CTA
//      (blockDim=64) so residency is 2048 thr/SM instead of the 1024 the
//      32-CTA/SM cap allows at blockDim=32. A row is exactly 32 float4, so
//      lane l privately accumulates column l — no smem, no barriers, exact
//      reference summation order (rel_err == 0).

static constexpr int D = 128;          // feature dim
static constexpr int D4 = D / 4;       // 32 float4 per row
static constexpr int WARPS_PER_CTA = 2;
static constexpr int MAX_SEGS = 1 << 20;

__device__ int g_seg_bounds[MAX_SEGS + 1];

__global__ void boundary_kernel(const int* __restrict__ seg_ids, int N, int S) {
    const int t = blockIdx.x * blockDim.x + threadIdx.x;
    const int base = t * 8;

    if (base < N) {
        if (base + 8 <= N) {
            // Fast path: two int4 loads cover ids[base..base+7].
            const int4 v0 = *reinterpret_cast<const int4*>(seg_ids + base);
            const int4 v1 = *reinterpret_cast<const int4*>(seg_ids + base + 4);
            int id[8] = {v0.x, v0.y, v0.z, v0.w, v1.x, v1.y, v1.z, v1.w};

            int prev;
            if (base == 0) {
                // head: segments 0..id[0] start at row 0
                for (int q = 0; q <= id[0]; q++) g_seg_bounds[q] = 0;
                prev = id[0];
            } else {
                prev = seg_ids[base - 1];   // L1-hit from neighbor's vector
            }

            #pragma unroll
            for (int j = 0; j < 8; j++) {
                if (prev != id[j])
                    for (int q = prev + 1; q <= id[j]; q++) g_seg_bounds[q] = base + j;
                prev = id[j];
            }

            if (base + 8 == N) {
                // tail: segments id[7]+1..S "start" at N (empty) + end sentinel
                for (int q = id[7] + 1; q <= S; q++) g_seg_bounds[q] = N;
            }
        } else {
            // Tail remainder (N not divisible by 8): scalar walk.
            int prev;
            if (base == 0) {
                const int id0 = seg_ids[0];
                for (int q = 0; q <= id0; q++) g_seg_bounds[q] = 0;
                prev = id0;
            } else {
                prev = seg_ids[base - 1];
            }
            for (int i = base; i < N; i++) {
                const int cur = seg_ids[i];
                if (prev != cur) for (int q = prev + 1; q <= cur; q++) g_seg_bounds[q] = i;
                prev = cur;
            }
            for (int q = prev + 1; q <= S; q++) g_seg_bounds[q] = N;
        }
    }

    // Allow the dependent seg_mean grid to begin launching.
    cudaTriggerProgrammaticLaunchCompletion();
}

__global__ __launch_bounds__(32 * WARPS_PER_CTA)
void seg_mean_kernel(const float* __restrict__ feats,
                     float* __restrict__ out,
                     int S) {
    const int warp = threadIdx.x >> 5;
    const int lane = threadIdx.x & 31;
    const int s = blockIdx.x * WARPS_PER_CTA + warp;

    const float4* __restrict__ f4 = reinterpret_cast<const float4*>(feats);

    // Wait for boundary_kernel's writes (no-op without PDL).
    cudaGridDependencySynchronize();

    if (s >= S) return;

    const int start = g_seg_bounds[s];
    const int end   = g_seg_bounds[s + 1];
    const int cnt   = end - start;

    float4 acc = make_float4(0.f, 0.f, 0.f, 0.f);

    // Lane l owns column l. 4x unrolled over consecutive rows: each unroll
    // iteration streams 4 rows x 512 B = 2 KB contiguous per warp.
    // __ldcs = evict-first: feats are read exactly once.
    int r = start;
    for (; r + 3 < end; r += 4) {
        float4 a = __ldcs(&f4[(size_t)r * D4 + lane]);
        float4 b = __ldcs(&f4[(size_t)(r + 1) * D4 + lane]);
        float4 c = __ldcs(&f4[(size_t)(r + 2) * D4 + lane]);
        float4 d = __ldcs(&f4[(size_t)(r + 3) * D4 + lane]);
        acc.x += a.x; acc.y += a.y; acc.z += a.z; acc.w += a.w;
        acc.x += b.x; acc.y += b.y; acc.z += b.z; acc.w += b.w;
        acc.x += c.x; acc.y += c.y; acc.z += c.z; acc.w += c.w;
        acc.x += d.x; acc.y += d.y; acc.z += d.z; acc.w += d.w;
    }
    for (; r < end; r++) {
        float4 a = __ldcs(&f4[(size_t)r * D4 + lane]);
        acc.x += a.x; acc.y += a.y; acc.z += a.z; acc.w += a.w;
    }

    // No reduction needed: lane's accumulator IS the output element.
    const float inv = 1.0f / (float)(cnt > 0 ? cnt : 1);
    acc.x *= inv; acc.y *= inv; acc.z *= inv; acc.w *= inv;
    reinterpret_cast<float4*>(out)[(size_t)s * D4 + lane] = acc;
}

extern "C" void kernel_launch(void* const* d_in, const int* in_sizes, int n_in,
                              void* d_out, int out_size) {
    const float* feats   = (const float*)d_in[0];
    const int*   seg_ids = (const int*)d_in[1];
    float*       out     = (float*)d_out;

    const int N = in_sizes[0] / D;       // number of rows in feats
    const int S = out_size / D;          // number of segments

    const int bthreads = 256;
    const int nvec     = (N + 7) / 8;
    const int bblocks  = (nvec + bthreads - 1) / bthreads;
    boundary_kernel<<<bblocks, bthreads>>>(seg_ids, N, S);

    const int grid = (S + WARPS_PER_CTA - 1) / WARPS_PER_CTA;

    // Dependent launch with PDL (neutral but harmless; falls back cleanly).
    cudaLaunchConfig_t cfg = {};
    cfg.gridDim = dim3((unsigned)grid);
    cfg.blockDim = dim3(32u * WARPS_PER_CTA);
    cfg.dynamicSmemBytes = 0;
    cfg.stream = 0;
    cudaLaunchAttribute attrs[1];
    attrs[0].id = cudaLaunchAttributeProgrammaticStreamSerialization;
    attrs[0].val.programmaticStreamSerializationAllowed = 1;
    cfg.attrs = attrs;
    cfg.numAttrs = 1;

    cudaError_t e = cudaLaunchKernelEx(&cfg, seg_mean_kernel, feats, out, S);
    if (e != cudaSuccess) {
        (void)cudaGetLastError();  // clear sticky error state
        seg_mean_kernel<<<grid, 32 * WARPS_PER_CTA>>>(feats, out, S);
    }
}